// round 12
// baseline (speedup 1.0000x reference)
#include <cuda_runtime.h>
#include <cstdint>

// Quaternion normalization: x viewed as (B, 256, 4); each 4-vector divided by
// its L2 norm (norm==0 -> divide by 1, i.e. pass through zeros).
// Total: 65536 * 1024 floats = 16,777,216 quaternions = 512 MiB R+W traffic.
//
// R12: 256-bit LSU ops (ld/st.global.v8.f32, sm_100+). Each warp memop covers
// a contiguous 1024B span (lane stride 32B), halving request count into
// L1tex/LTS vs the 128-bit R8 winner. Everything else identical: 4 quats per
// thread, block-interleaved, .cs streaming policy, 16384-block launch.

struct f4x2 { float4 a, b; };

__device__ __forceinline__ f4x2 ldg_cs_f8(const float4* p) {
    f4x2 v;
    asm volatile("ld.global.cs.v8.f32 {%0,%1,%2,%3,%4,%5,%6,%7}, [%8];"
                 : "=f"(v.a.x), "=f"(v.a.y), "=f"(v.a.z), "=f"(v.a.w),
                   "=f"(v.b.x), "=f"(v.b.y), "=f"(v.b.z), "=f"(v.b.w)
                 : "l"(p));
    return v;
}

__device__ __forceinline__ void stg_cs_f8(float4* p, f4x2 v) {
    asm volatile("st.global.cs.v8.f32 [%0], {%1,%2,%3,%4,%5,%6,%7,%8};"
                 :: "l"(p),
                    "f"(v.a.x), "f"(v.a.y), "f"(v.a.z), "f"(v.a.w),
                    "f"(v.b.x), "f"(v.b.y), "f"(v.b.z), "f"(v.b.w));
}

__device__ __forceinline__ float4 norm_quat(float4 q) {
    float s = q.x * q.x + q.y * q.y + q.z * q.z + q.w * q.w;
    float inv = (s == 0.0f) ? 1.0f : rsqrtf(s);
    q.x *= inv; q.y *= inv; q.z *= inv; q.w *= inv;
    return q;
}

// Bulk kernel: branch-free, 4 quaternions per thread as 2x 256-bit ops.
// Index: thread t owns float4 pair starting at block_base + 2*t, and the
// second pair at +2*T float4s. Lane stride 32B -> each warp v8 op spans a
// contiguous 1024B block. Loads front-batched for MLP=2 (x1024B).
__global__ void __launch_bounds__(256) quat_norm_bulk(
    const float4* __restrict__ in, float4* __restrict__ out)
{
    const int T = 256;
    int64_t base = (int64_t)blockIdx.x * (T * 4) + (int64_t)threadIdx.x * 2;
    f4x2 p0 = ldg_cs_f8(in + base);
    f4x2 p1 = ldg_cs_f8(in + base + 2 * T);
    p0.a = norm_quat(p0.a);
    p0.b = norm_quat(p0.b);
    p1.a = norm_quat(p1.a);
    p1.b = norm_quat(p1.b);
    stg_cs_f8(out + base, p0);
    stg_cs_f8(out + base + 2 * T, p1);
}

// Tail kernel: one quaternion per thread with bounds check (empty for this
// problem's shape; kept for generality).
__global__ void __launch_bounds__(256) quat_norm_tail(
    const float4* __restrict__ in, float4* __restrict__ out,
    int64_t start, int64_t n_quats)
{
    int64_t i = start + (int64_t)blockIdx.x * blockDim.x + threadIdx.x;
    if (i < n_quats) {
        float4 q = in[i];
        out[i] = norm_quat(q);
    }
}

extern "C" void kernel_launch(void* const* d_in, const int* in_sizes, int n_in,
                              void* d_out, int out_size) {
    const float4* in = (const float4*)d_in[0];
    float4* out = (float4*)d_out;
    int64_t n_quats = (int64_t)in_sizes[0] / 4;   // 16,777,216

    const int threads = 256;
    const int64_t quats_per_block = (int64_t)threads * 4;   // 1024
    int64_t bulk_blocks = n_quats / quats_per_block;        // 16384 (exact)

    if (bulk_blocks > 0)
        quat_norm_bulk<<<(unsigned)bulk_blocks, threads>>>(in, out);

    int64_t done = bulk_blocks * quats_per_block;
    int64_t rem = n_quats - done;
    if (rem > 0) {
        int tail_blocks = (int)((rem + threads - 1) / threads);
        quat_norm_tail<<<tail_blocks, threads>>>(in, out, done, n_quats);
    }
}

// round 14
// speedup vs baseline: 1.0008x; 1.0008x over previous
#include <cuda_runtime.h>
#include <cstdint>

// Quaternion normalization: x viewed as (B, 256, 4); each 4-vector divided by
// its L2 norm (norm==0 -> divide by 1, i.e. pass through zeros).
// Total: 65536 * 1024 floats = 16,777,216 quaternions = 512 MiB R+W traffic.
//
// FINAL (R8 canonical winner; 3x reproduced at 81.98us, DRAM 82%).
// HBM-bound at the 1:1 R/W sustained ceiling (~6.55 TB/s). Exhaustive matrix
// R2-R12: coalescing (lane stride 16B per LDG.128, block-interleaved) was the
// only lever that mattered (-6%); unroll depth, store policy (.cs/.wb),
// occupancy, launch topology (persistent regressed -13%), L2::256B hint, and
// 256-bit v8 LSU ops were all neutral. SM side idles at 15% issue; the memory
// system is byte-limited, not request-limited.

__device__ __forceinline__ float4 ldg_cs_f4(const float4* p) {
    float4 v;
    asm volatile("ld.global.cs.v4.f32 {%0,%1,%2,%3}, [%4];"
                 : "=f"(v.x), "=f"(v.y), "=f"(v.z), "=f"(v.w)
                 : "l"(p));
    return v;
}

__device__ __forceinline__ void stg_cs_f4(float4* p, float4 v) {
    asm volatile("st.global.cs.v4.f32 [%0], {%1,%2,%3,%4};"
                 :: "l"(p), "f"(v.x), "f"(v.y), "f"(v.z), "f"(v.w));
}

__device__ __forceinline__ float4 norm_quat(float4 q) {
    float s = q.x * q.x + q.y * q.y + q.z * q.z + q.w * q.w;
    float inv = (s == 0.0f) ? 1.0f : rsqrtf(s);
    q.x *= inv; q.y *= inv; q.z *= inv; q.w *= inv;
    return q;
}

// Bulk kernel: branch-free, 4 quaternions per thread, interleaved within the
// block (index = block_base + tid + k*blockDim) so every LDG.128/STG.128 is
// fully coalesced (lane stride 16B -> 4 contiguous 128B lines per wavefront).
// Loads front-batched for MLP=4.
__global__ void __launch_bounds__(256) quat_norm_bulk(
    const float4* __restrict__ in, float4* __restrict__ out)
{
    const int T = 256;
    int64_t base = (int64_t)blockIdx.x * (T * 4) + threadIdx.x;
    float4 a = ldg_cs_f4(in + base + 0 * T);
    float4 b = ldg_cs_f4(in + base + 1 * T);
    float4 c = ldg_cs_f4(in + base + 2 * T);
    float4 d = ldg_cs_f4(in + base + 3 * T);
    a = norm_quat(a);
    b = norm_quat(b);
    c = norm_quat(c);
    d = norm_quat(d);
    stg_cs_f4(out + base + 0 * T, a);
    stg_cs_f4(out + base + 1 * T, b);
    stg_cs_f4(out + base + 2 * T, c);
    stg_cs_f4(out + base + 3 * T, d);
}

// Tail kernel: one quaternion per thread with bounds check (empty for this
// problem's shape; kept for generality).
__global__ void __launch_bounds__(256) quat_norm_tail(
    const float4* __restrict__ in, float4* __restrict__ out,
    int64_t start, int64_t n_quats)
{
    int64_t i = start + (int64_t)blockIdx.x * blockDim.x + threadIdx.x;
    if (i < n_quats) {
        float4 a = ldg_cs_f4(in + i);
        stg_cs_f4(out + i, norm_quat(a));
    }
}

extern "C" void kernel_launch(void* const* d_in, const int* in_sizes, int n_in,
                              void* d_out, int out_size) {
    const float4* in = (const float4*)d_in[0];
    float4* out = (float4*)d_out;
    int64_t n_quats = (int64_t)in_sizes[0] / 4;   // 16,777,216

    const int threads = 256;
    const int64_t quats_per_block = (int64_t)threads * 4;   // 1024
    int64_t bulk_blocks = n_quats / quats_per_block;        // 16384 (exact)

    if (bulk_blocks > 0)
        quat_norm_bulk<<<(unsigned)bulk_blocks, threads>>>(in, out);

    int64_t done = bulk_blocks * quats_per_block;
    int64_t rem = n_quats - done;
    if (rem > 0) {
        int tail_blocks = (int)((rem + threads - 1) / threads);
        quat_norm_tail<<<tail_blocks, threads>>>(in, out, done, n_quats);
    }
}